// round 1
// baseline (speedup 1.0000x reference)
#include <cuda_runtime.h>
#include <math.h>

#define N_TOKENS  16384
#define D_MODEL   1024
#define D_FF      2048
#define N_EXPERTS 4
#define LN_EPS    1e-6f

// Scratch (static __device__ arrays per allocation rules)
__device__ float g_h[(size_t)N_TOKENS * D_FF];      // gelu(x@w1^T+b1), compacted rows
__device__ float g_z[(size_t)N_TOKENS * D_MODEL];   // x + h@w2^T + b2, compacted rows
__device__ float g_comb[N_TOKENS * N_EXPERTS];      // dense routing weights
__device__ int   g_idx[N_EXPERTS][N_TOKENS];        // per-expert token lists
__device__ int   g_count[N_EXPERTS];

__device__ __forceinline__ float gelu_exact(float v) {
    return 0.5f * v * (1.0f + erff(v * 0.70710678118654752f));
}

// ---------------------------------------------------------------------------
// Zero output accumulator + routing counters (runs first every call)
// ---------------------------------------------------------------------------
__global__ void init_kernel(float* __restrict__ y) {
    int stride = gridDim.x * blockDim.x;
    for (int i = blockIdx.x * blockDim.x + threadIdx.x;
         i < N_TOKENS * D_MODEL; i += stride)
        y[i] = 0.0f;
    if (blockIdx.x == 0 && threadIdx.x < N_EXPERTS)
        g_count[threadIdx.x] = 0;
}

// ---------------------------------------------------------------------------
// Gating: scores = x @ gate_w^T, top-2 softmax, build per-expert index lists
// One warp per token.
// ---------------------------------------------------------------------------
__global__ void route_kernel(const float* __restrict__ x,
                             const float* __restrict__ gw) {
    int warp = (blockIdx.x * blockDim.x + threadIdx.x) >> 5;
    int lane = threadIdx.x & 31;
    if (warp >= N_TOKENS) return;

    const float* xr = x + (size_t)warp * D_MODEL;
    float s0 = 0.f, s1 = 0.f, s2 = 0.f, s3 = 0.f;
    for (int i = lane; i < D_MODEL; i += 32) {
        float xv = xr[i];
        s0 += xv * gw[0 * D_MODEL + i];
        s1 += xv * gw[1 * D_MODEL + i];
        s2 += xv * gw[2 * D_MODEL + i];
        s3 += xv * gw[3 * D_MODEL + i];
    }
#pragma unroll
    for (int o = 16; o; o >>= 1) {
        s0 += __shfl_xor_sync(0xffffffffu, s0, o);
        s1 += __shfl_xor_sync(0xffffffffu, s1, o);
        s2 += __shfl_xor_sync(0xffffffffu, s2, o);
        s3 += __shfl_xor_sync(0xffffffffu, s3, o);
    }
    if (lane == 0) {
        float s[4] = {s0, s1, s2, s3};
        // top-2, lowest index wins ties (matches lax.top_k)
        int i0 = 0;
#pragma unroll
        for (int e = 1; e < 4; e++) if (s[e] > s[i0]) i0 = e;
        int i1 = -1;
#pragma unroll
        for (int e = 0; e < 4; e++) {
            if (e == i0) continue;
            if (i1 < 0 || s[e] > s[i1]) i1 = e;
        }
        float m  = fmaxf(s[i0], s[i1]);
        float e0 = expf(s[i0] - m);
        float e1 = expf(s[i1] - m);
        float inv = 1.0f / (e0 + e1);
        float c[4] = {0.f, 0.f, 0.f, 0.f};
        c[i0] = e0 * inv;
        c[i1] = e1 * inv;
#pragma unroll
        for (int e = 0; e < 4; e++) g_comb[warp * N_EXPERTS + e] = c[e];

        int p0 = atomicAdd(&g_count[i0], 1);
        g_idx[i0][p0] = warp;
        int p1 = atomicAdd(&g_count[i1], 1);
        g_idx[i1][p1] = warp;
    }
}

// ---------------------------------------------------------------------------
// Tiled SGEMM, 128x128x16, 256 threads, 8x8 microtile.
// MODE 0: h[r][n] = gelu( x[idx[r]] @ w1^T + b1 )    (gathered A rows)
// MODE 1: z[r][n] = x[idx[r]][n] + (h[r] @ w2^T)[n] + b2[n]
// Rows are compacted per-expert (r < g_count[e]); CTAs past count exit.
// ---------------------------------------------------------------------------
template <int MODE>
__global__ __launch_bounds__(256, 2)
void gemm_kernel(const float* __restrict__ x,
                 const float* __restrict__ B,     // w1[e] or w2[e]
                 const float* __restrict__ bias,  // b1[e] or b2[e]
                 int e) {
    constexpr int BM = 128, BN = 128, BK = 16;
    constexpr int K    = (MODE == 0) ? D_MODEL : D_FF;
    constexpr int Nout = (MODE == 0) ? D_FF    : D_MODEL;

    const int count = g_count[e];
    const int m0 = blockIdx.y * BM;
    if (m0 >= count) return;
    const int n0 = blockIdx.x * BN;

    __shared__ float As[BK][BM];
    __shared__ float Bs[BK][BN];

    const int tid   = threadIdx.x;
    const int a_row = tid >> 2;   // 0..63
    const int a_k4  = tid & 3;    // float4 slot in K

    const float* aptr[2];
#pragma unroll
    for (int p = 0; p < 2; p++) {
        int r  = a_row + p * 64;
        int gr = m0 + r;
        int src;
        if (MODE == 0) src = (gr < count) ? g_idx[e][gr] : 0;
        else           src = (gr < count) ? gr : 0;
        aptr[p] = (MODE == 0) ? (x + (size_t)src * D_MODEL)
                              : (g_h + (size_t)src * D_FF);
    }
    const float* bptr[2];
#pragma unroll
    for (int p = 0; p < 2; p++)
        bptr[p] = B + (size_t)(n0 + a_row + p * 64) * K;

    const int rm = (tid >> 4) * 8;
    const int rn = (tid & 15) * 8;

    float acc[8][8];
#pragma unroll
    for (int i = 0; i < 8; i++)
#pragma unroll
        for (int j = 0; j < 8; j++) acc[i][j] = 0.0f;

    for (int k0 = 0; k0 < K; k0 += BK) {
#pragma unroll
        for (int p = 0; p < 2; p++) {
            int r = a_row + p * 64;
            float4 av = *(const float4*)(aptr[p] + k0 + a_k4 * 4);
            As[a_k4 * 4 + 0][r] = av.x;
            As[a_k4 * 4 + 1][r] = av.y;
            As[a_k4 * 4 + 2][r] = av.z;
            As[a_k4 * 4 + 3][r] = av.w;
            float4 bv = *(const float4*)(bptr[p] + k0 + a_k4 * 4);
            Bs[a_k4 * 4 + 0][r] = bv.x;
            Bs[a_k4 * 4 + 1][r] = bv.y;
            Bs[a_k4 * 4 + 2][r] = bv.z;
            Bs[a_k4 * 4 + 3][r] = bv.w;
        }
        __syncthreads();
#pragma unroll
        for (int kk = 0; kk < BK; kk++) {
            float af[8], bf[8];
#pragma unroll
            for (int i = 0; i < 8; i++) af[i] = As[kk][rm + i];
#pragma unroll
            for (int j = 0; j < 8; j++) bf[j] = Bs[kk][rn + j];
#pragma unroll
            for (int i = 0; i < 8; i++)
#pragma unroll
                for (int j = 0; j < 8; j++) acc[i][j] += af[i] * bf[j];
        }
        __syncthreads();
    }

    // Epilogue
#pragma unroll
    for (int i = 0; i < 8; i++) {
        int gr = m0 + rm + i;
        if (gr >= count) continue;
        int tok = 0;
        if (MODE == 1) tok = g_idx[e][gr];
#pragma unroll
        for (int jj = 0; jj < 2; jj++) {
            int n = n0 + rn + jj * 4;
            float4 bz = *(const float4*)(bias + n);
            float4 o;
            float v0 = acc[i][jj * 4 + 0] + bz.x;
            float v1 = acc[i][jj * 4 + 1] + bz.y;
            float v2 = acc[i][jj * 4 + 2] + bz.z;
            float v3 = acc[i][jj * 4 + 3] + bz.w;
            if (MODE == 0) {
                o.x = gelu_exact(v0);
                o.y = gelu_exact(v1);
                o.z = gelu_exact(v2);
                o.w = gelu_exact(v3);
                *(float4*)(g_h + (size_t)gr * Nout + n) = o;
            } else {
                float4 xr = *(const float4*)(x + (size_t)tok * D_MODEL + n);
                o.x = v0 + xr.x;
                o.y = v1 + xr.y;
                o.z = v2 + xr.z;
                o.w = v3 + xr.w;
                *(float4*)(g_z + (size_t)gr * Nout + n) = o;
            }
        }
    }
}

// ---------------------------------------------------------------------------
// Rowwise LayerNorm of z + weighted accumulate into y.
// One block (256 threads) per compacted row; 4 floats/thread (d=1024).
// ---------------------------------------------------------------------------
__global__ void ln_accum_kernel(const float* __restrict__ gamma,
                                const float* __restrict__ beta,
                                float* __restrict__ y, int e) {
    int r = blockIdx.x;
    if (r >= g_count[e]) return;
    int tok = g_idx[e][r];
    float w = g_comb[tok * N_EXPERTS + e];

    int tid = threadIdx.x;
    float4 v = *(const float4*)(g_z + (size_t)r * D_MODEL + tid * 4);
    float s  = v.x + v.y + v.z + v.w;
    float ss = v.x * v.x + v.y * v.y + v.z * v.z + v.w * v.w;

    __shared__ float sh[2][8];
    __shared__ float mu_s, rstd_s;
#pragma unroll
    for (int o = 16; o; o >>= 1) {
        s  += __shfl_xor_sync(0xffffffffu, s, o);
        ss += __shfl_xor_sync(0xffffffffu, ss, o);
    }
    int warp = tid >> 5, lane = tid & 31;
    if (lane == 0) { sh[0][warp] = s; sh[1][warp] = ss; }
    __syncthreads();
    if (tid == 0) {
        float S = 0.f, SS = 0.f;
#pragma unroll
        for (int i = 0; i < 8; i++) { S += sh[0][i]; SS += sh[1][i]; }
        float mu  = S * (1.0f / D_MODEL);
        float var = SS * (1.0f / D_MODEL) - mu * mu;
        mu_s   = mu;
        rstd_s = rsqrtf(var + LN_EPS);
    }
    __syncthreads();
    float mu = mu_s, rstd = rstd_s;

    float4 g4 = *(const float4*)(gamma + tid * 4);
    float4 b4 = *(const float4*)(beta + tid * 4);
    float* yp = y + (size_t)tok * D_MODEL + tid * 4;
    float4 yo = *(float4*)yp;
    yo.x += w * ((v.x - mu) * rstd * g4.x + b4.x);
    yo.y += w * ((v.y - mu) * rstd * g4.y + b4.y);
    yo.z += w * ((v.z - mu) * rstd * g4.z + b4.z);
    yo.w += w * ((v.w - mu) * rstd * g4.w + b4.w);
    *(float4*)yp = yo;
}

// ---------------------------------------------------------------------------
extern "C" void kernel_launch(void* const* d_in, const int* in_sizes, int n_in,
                              void* d_out, int out_size) {
    const float* x     = (const float*)d_in[0];
    const float* gw    = (const float*)d_in[1];
    const float* w1    = (const float*)d_in[2];
    const float* b1    = (const float*)d_in[3];
    const float* w2    = (const float*)d_in[4];
    const float* b2    = (const float*)d_in[5];
    const float* gamma = (const float*)d_in[6];
    const float* beta  = (const float*)d_in[7];
    float* y = (float*)d_out;

    init_kernel<<<512, 256>>>(y);
    route_kernel<<<(N_TOKENS * 32) / 256, 256>>>(x, gw);

    for (int e = 0; e < N_EXPERTS; e++) {
        gemm_kernel<0><<<dim3(D_FF / 128, N_TOKENS / 128), 256>>>(
            x, w1 + (size_t)e * D_FF * D_MODEL, b1 + e * D_FF, e);
        gemm_kernel<1><<<dim3(D_MODEL / 128, N_TOKENS / 128), 256>>>(
            x, w2 + (size_t)e * D_MODEL * D_FF, b2 + e * D_MODEL, e);
        ln_accum_kernel<<<N_TOKENS, 256>>>(gamma + e * D_MODEL,
                                           beta + e * D_MODEL, y, e);
    }
}

// round 3
// speedup vs baseline: 2.9628x; 2.9628x over previous
#include <cuda_runtime.h>
#include <cuda_bf16.h>
#include <math.h>

#define N_TOKENS  16384
#define D_MODEL   1024
#define D_FF      2048
#define N_EXPERTS 4
#define LN_EPS    1e-6f

// ------------------------- static device scratch ---------------------------
__device__ __align__(16) __nv_bfloat16 g_xh[(size_t)N_TOKENS * D_MODEL];
__device__ __align__(16) __nv_bfloat16 g_xl[(size_t)N_TOKENS * D_MODEL];
__device__ __align__(16) __nv_bfloat16 g_w1h[(size_t)N_EXPERTS * D_FF * D_MODEL];
__device__ __align__(16) __nv_bfloat16 g_w1l[(size_t)N_EXPERTS * D_FF * D_MODEL];
__device__ __align__(16) __nv_bfloat16 g_w2h[(size_t)N_EXPERTS * D_MODEL * D_FF];
__device__ __align__(16) __nv_bfloat16 g_w2l[(size_t)N_EXPERTS * D_MODEL * D_FF];
__device__ __align__(16) __nv_bfloat16 g_hh[(size_t)N_TOKENS * D_FF];
__device__ __align__(16) __nv_bfloat16 g_hl[(size_t)N_TOKENS * D_FF];
__device__ __align__(16) float g_z[(size_t)N_TOKENS * D_MODEL];
__device__ float g_comb[N_TOKENS * N_EXPERTS];
__device__ int   g_idx[N_EXPERTS][N_TOKENS];
__device__ int   g_count[N_EXPERTS];

__device__ __forceinline__ float gelu_exact(float v) {
    return 0.5f * v * (1.0f + erff(v * 0.70710678118654752f));
}

// --------------------------- tiny PTX helpers ------------------------------
__device__ __forceinline__ void ldsm_x4(unsigned* r, unsigned addr) {
    asm volatile("ldmatrix.sync.aligned.m8n8.x4.shared.b16 {%0,%1,%2,%3}, [%4];"
                 : "=r"(r[0]), "=r"(r[1]), "=r"(r[2]), "=r"(r[3]) : "r"(addr));
}
__device__ __forceinline__ void mma16816(float* c, const unsigned* a, const unsigned* b) {
    asm volatile("mma.sync.aligned.m16n8k16.row.col.f32.bf16.bf16.f32 "
                 "{%0,%1,%2,%3}, {%4,%5,%6,%7}, {%8,%9}, {%0,%1,%2,%3};"
                 : "+f"(c[0]), "+f"(c[1]), "+f"(c[2]), "+f"(c[3])
                 : "r"(a[0]), "r"(a[1]), "r"(a[2]), "r"(a[3]), "r"(b[0]), "r"(b[1]));
}
#define CP_ASYNC16(s, g) \
    asm volatile("cp.async.cg.shared.global [%0], [%1], 16;" :: "r"(s), "l"(g) : "memory")
#define CP_COMMIT() asm volatile("cp.async.commit_group;" ::: "memory")
#define CP_WAIT1()  asm volatile("cp.async.wait_group 1;" ::: "memory")

// ---------------------------------------------------------------------------
// init: zero y + routing counters
// ---------------------------------------------------------------------------
__global__ void init_kernel(float* __restrict__ y) {
    int stride = gridDim.x * blockDim.x;
    for (int i = blockIdx.x * blockDim.x + threadIdx.x;
         i < N_TOKENS * D_MODEL; i += stride)
        y[i] = 0.0f;
    if (blockIdx.x == 0 && threadIdx.x < N_EXPERTS)
        g_count[threadIdx.x] = 0;
}

// ---------------------------------------------------------------------------
// split fp32 -> (hi, lo) bf16 pair arrays
// ---------------------------------------------------------------------------
__global__ void split_kernel(const float4* __restrict__ src,
                             __nv_bfloat162* __restrict__ hi,
                             __nv_bfloat162* __restrict__ lo, int n4) {
    int stride = gridDim.x * blockDim.x;
    for (int i = blockIdx.x * blockDim.x + threadIdx.x; i < n4; i += stride) {
        float4 v = src[i];
        __nv_bfloat16 h0 = __float2bfloat16_rn(v.x);
        __nv_bfloat16 h1 = __float2bfloat16_rn(v.y);
        __nv_bfloat16 h2 = __float2bfloat16_rn(v.z);
        __nv_bfloat16 h3 = __float2bfloat16_rn(v.w);
        __nv_bfloat16 l0 = __float2bfloat16_rn(v.x - __bfloat162float(h0));
        __nv_bfloat16 l1 = __float2bfloat16_rn(v.y - __bfloat162float(h1));
        __nv_bfloat16 l2 = __float2bfloat16_rn(v.z - __bfloat162float(h2));
        __nv_bfloat16 l3 = __float2bfloat16_rn(v.w - __bfloat162float(h3));
        hi[2 * i]     = __nv_bfloat162{h0, h1};
        hi[2 * i + 1] = __nv_bfloat162{h2, h3};
        lo[2 * i]     = __nv_bfloat162{l0, l1};
        lo[2 * i + 1] = __nv_bfloat162{l2, l3};
    }
}

// ---------------------------------------------------------------------------
// Gating (fp32, unchanged): top-2 softmax + per-expert compaction
// ---------------------------------------------------------------------------
__global__ void route_kernel(const float* __restrict__ x,
                             const float* __restrict__ gw) {
    int warp = (blockIdx.x * blockDim.x + threadIdx.x) >> 5;
    int lane = threadIdx.x & 31;
    if (warp >= N_TOKENS) return;

    const float* xr = x + (size_t)warp * D_MODEL;
    float s0 = 0.f, s1 = 0.f, s2 = 0.f, s3 = 0.f;
    for (int i = lane; i < D_MODEL; i += 32) {
        float xv = xr[i];
        s0 += xv * gw[0 * D_MODEL + i];
        s1 += xv * gw[1 * D_MODEL + i];
        s2 += xv * gw[2 * D_MODEL + i];
        s3 += xv * gw[3 * D_MODEL + i];
    }
#pragma unroll
    for (int o = 16; o; o >>= 1) {
        s0 += __shfl_xor_sync(0xffffffffu, s0, o);
        s1 += __shfl_xor_sync(0xffffffffu, s1, o);
        s2 += __shfl_xor_sync(0xffffffffu, s2, o);
        s3 += __shfl_xor_sync(0xffffffffu, s3, o);
    }
    if (lane == 0) {
        float s[4] = {s0, s1, s2, s3};
        int i0 = 0;
#pragma unroll
        for (int e = 1; e < 4; e++) if (s[e] > s[i0]) i0 = e;
        int i1 = -1;
#pragma unroll
        for (int e = 0; e < 4; e++) {
            if (e == i0) continue;
            if (i1 < 0 || s[e] > s[i1]) i1 = e;
        }
        float m  = fmaxf(s[i0], s[i1]);
        float e0 = expf(s[i0] - m);
        float e1 = expf(s[i1] - m);
        float inv = 1.0f / (e0 + e1);
        float c[4] = {0.f, 0.f, 0.f, 0.f};
        c[i0] = e0 * inv;
        c[i1] = e1 * inv;
#pragma unroll
        for (int e = 0; e < 4; e++) g_comb[warp * N_EXPERTS + e] = c[e];
        int p0 = atomicAdd(&g_count[i0], 1);
        g_idx[i0][p0] = warp;
        int p1 = atomicAdd(&g_count[i1], 1);
        g_idx[i1][p1] = warp;
    }
}

// ---------------------------------------------------------------------------
// 3xbf16 split-precision MMA GEMM.  C = A @ B^T (+epilogue)
// BM=128 BN=128 BK=32, 256 thr, 8 warps (2x4), warp tile 64x32, 2-stage
// cp.async pipeline, XOR-swizzled smem, ldmatrix fragments.
// MODE 0: A = x(hi/lo) gathered rows, B = w1 -> h(hi/lo) = gelu(.+b1)
// MODE 1: A = h(hi/lo) compacted,     B = w2 -> z = x[tok] + . + b2  (fp32)
// ---------------------------------------------------------------------------
#define STAGE_BYTES 32768
#define SA_HI 0
#define SA_LO 8192
#define SB_HI 16384
#define SB_LO 24576

template <int MODE>
__global__ __launch_bounds__(256, 2)
void gemm_mma(const __nv_bfloat16* __restrict__ Bh,
              const __nv_bfloat16* __restrict__ Bl,
              const float* __restrict__ bias,
              const float* __restrict__ x, int e) {
    constexpr int K  = (MODE == 0) ? D_MODEL : D_FF;
    constexpr int NO = (MODE == 0) ? D_FF    : D_MODEL;
    constexpr int KT = K / 32;

    const int count = g_count[e];
    const int m0 = blockIdx.y * 128;
    if (m0 >= count) return;
    const int n0 = blockIdx.x * 128;

    extern __shared__ __align__(16) char dynsmem[];
    const unsigned sbase = (unsigned)__cvta_generic_to_shared(dynsmem);

    const int tid  = threadIdx.x;
    const int lane = tid & 31;
    const int wid  = tid >> 5;
    const int m_warp = (wid >> 2) * 64;   // 0 or 64
    const int n_warp = (wid & 3) * 32;    // 0..96

    // ---- cp.async source pointers (per thread: 2 rows x 1 chunk per array)
    const int rA0 = tid >> 2;          // 0..63
    const int rA1 = rA0 + 64;
    const int ck  = tid & 3;           // 16B chunk within 64B row

    const __nv_bfloat16* Ah = (MODE == 0) ? g_xh : g_hh;
    const __nv_bfloat16* Al = (MODE == 0) ? g_xl : g_hl;

    int gr0 = m0 + rA0, gr1 = m0 + rA1;
    int s0, s1;
    if (MODE == 0) {
        s0 = g_idx[e][(gr0 < count) ? gr0 : 0];
        s1 = g_idx[e][(gr1 < count) ? gr1 : 0];
    } else {
        s0 = (gr0 < count) ? gr0 : 0;
        s1 = (gr1 < count) ? gr1 : 0;
    }
    const __nv_bfloat16* pAh0 = Ah + (size_t)s0 * K + ck * 8;
    const __nv_bfloat16* pAh1 = Ah + (size_t)s1 * K + ck * 8;
    const __nv_bfloat16* pAl0 = Al + (size_t)s0 * K + ck * 8;
    const __nv_bfloat16* pAl1 = Al + (size_t)s1 * K + ck * 8;
    const __nv_bfloat16* pBh0 = Bh + (size_t)(n0 + rA0) * K + ck * 8;
    const __nv_bfloat16* pBh1 = Bh + (size_t)(n0 + rA1) * K + ck * 8;
    const __nv_bfloat16* pBl0 = Bl + (size_t)(n0 + rA0) * K + ck * 8;
    const __nv_bfloat16* pBl1 = Bl + (size_t)(n0 + rA1) * K + ck * 8;

    // swizzled smem store offsets (same for A and B regions)
    const unsigned sOf0 = rA0 * 64 + ((ck ^ ((rA0 >> 1) & 3)) << 4);
    const unsigned sOf1 = rA1 * 64 + ((ck ^ ((rA1 >> 1) & 3)) << 4);

    // ---- ldmatrix offsets
    unsigned rowtermA[4], swzA[4];
#pragma unroll
    for (int mt = 0; mt < 4; mt++) {
        int r = m_warp + mt * 16 + (lane & 7) + ((lane >> 3) & 1) * 8;
        rowtermA[mt] = r * 64;
        swzA[mt]     = (r >> 1) & 3;
    }
    const unsigned g2A = lane >> 4;  // 0/1: k-chunk half select
    unsigned offB[4];
#pragma unroll
    for (int nt = 0; nt < 4; nt++) {
        int r = n_warp + nt * 8 + (lane & 7);
        unsigned g = lane >> 3;     // 0..3 -> k-chunks 0..3
        offB[nt] = r * 64 + ((g ^ ((r >> 1) & 3)) << 4);
    }

    float acc[4][4][4];
#pragma unroll
    for (int mt = 0; mt < 4; mt++)
#pragma unroll
        for (int nt = 0; nt < 4; nt++)
#pragma unroll
            for (int i = 0; i < 4; i++) acc[mt][nt][i] = 0.f;

#define ISSUE(kt)                                                      \
    do {                                                               \
        unsigned sb = sbase + ((kt) & 1) * STAGE_BYTES;                \
        int kb = (kt) * 32;                                            \
        CP_ASYNC16(sb + SA_HI + sOf0, pAh0 + kb);                      \
        CP_ASYNC16(sb + SA_HI + sOf1, pAh1 + kb);                      \
        CP_ASYNC16(sb + SA_LO + sOf0, pAl0 + kb);                      \
        CP_ASYNC16(sb + SA_LO + sOf1, pAl1 + kb);                      \
        CP_ASYNC16(sb + SB_HI + sOf0, pBh0 + kb);                      \
        CP_ASYNC16(sb + SB_HI + sOf1, pBh1 + kb);                      \
        CP_ASYNC16(sb + SB_LO + sOf0, pBl0 + kb);                      \
        CP_ASYNC16(sb + SB_LO + sOf1, pBl1 + kb);                      \
    } while (0)

    ISSUE(0);
    CP_COMMIT();

    for (int kt = 0; kt < KT; kt++) {
        if (kt + 1 < KT) ISSUE(kt + 1);
        CP_COMMIT();
        CP_WAIT1();
        __syncthreads();

        const unsigned sb = sbase + (kt & 1) * STAGE_BYTES;
        // B fragments for full 32-k tile
        unsigned bh[4][4], bl[4][4];
#pragma unroll
        for (int nt = 0; nt < 4; nt++) {
            ldsm_x4(bh[nt], sb + SB_HI + offB[nt]);
            ldsm_x4(bl[nt], sb + SB_LO + offB[nt]);
        }
#pragma unroll
        for (int k16 = 0; k16 < 2; k16++) {
#pragma unroll
            for (int mt = 0; mt < 4; mt++) {
                unsigned offA = rowtermA[mt] + (((k16 * 2 + g2A) ^ swzA[mt]) << 4);
                unsigned ah[4], al[4];
                ldsm_x4(ah, sb + SA_HI + offA);
                ldsm_x4(al, sb + SA_LO + offA);
#pragma unroll
                for (int nt = 0; nt < 4; nt++) {
                    mma16816(acc[mt][nt], ah, &bh[nt][k16 * 2]);
                    mma16816(acc[mt][nt], ah, &bl[nt][k16 * 2]);
                    mma16816(acc[mt][nt], al, &bh[nt][k16 * 2]);
                }
            }
        }
        __syncthreads();
    }

    // ---- epilogue
#pragma unroll
    for (int nt = 0; nt < 4; nt++) {
        const int col = n0 + n_warp + nt * 8 + (lane & 3) * 2;
        const float bz0 = bias[col], bz1 = bias[col + 1];
#pragma unroll
        for (int mt = 0; mt < 4; mt++) {
#pragma unroll
            for (int half = 0; half < 2; half++) {
                int gr = m0 + m_warp + mt * 16 + (lane >> 2) + half * 8;
                if (gr >= count) continue;
                float v0 = acc[mt][nt][half * 2 + 0] + bz0;
                float v1 = acc[mt][nt][half * 2 + 1] + bz1;
                if (MODE == 0) {
                    v0 = gelu_exact(v0);
                    v1 = gelu_exact(v1);
                    __nv_bfloat16 h0 = __float2bfloat16_rn(v0);
                    __nv_bfloat16 h1 = __float2bfloat16_rn(v1);
                    __nv_bfloat16 l0 = __float2bfloat16_rn(v0 - __bfloat162float(h0));
                    __nv_bfloat16 l1 = __float2bfloat16_rn(v1 - __bfloat162float(h1));
                    *(__nv_bfloat162*)&g_hh[(size_t)gr * NO + col] = __nv_bfloat162{h0, h1};
                    *(__nv_bfloat162*)&g_hl[(size_t)gr * NO + col] = __nv_bfloat162{l0, l1};
                } else {
                    int tok = g_idx[e][gr];
                    const float* xr = x + (size_t)tok * D_MODEL + col;
                    float2 o;
                    o.x = v0 + xr[0];
                    o.y = v1 + xr[1];
                    *(float2*)&g_z[(size_t)gr * NO + col] = o;
                }
            }
        }
    }
#undef ISSUE
}

// ---------------------------------------------------------------------------
// Rowwise LayerNorm of z + weighted accumulate into y.
// ---------------------------------------------------------------------------
__global__ void ln_accum_kernel(const float* __restrict__ gamma,
                                const float* __restrict__ beta,
                                float* __restrict__ y, int e) {
    int r = blockIdx.x;
    if (r >= g_count[e]) return;
    int tok = g_idx[e][r];
    float w = g_comb[tok * N_EXPERTS + e];

    int tid = threadIdx.x;
    float4 v = *(const float4*)(g_z + (size_t)r * D_MODEL + tid * 4);
    float s  = v.x + v.y + v.z + v.w;
    float ss = v.x * v.x + v.y * v.y + v.z * v.z + v.w * v.w;

    __shared__ float sh[2][8];
    __shared__ float mu_s, rstd_s;
#pragma unroll
    for (int o = 16; o; o >>= 1) {
        s  += __shfl_xor_sync(0xffffffffu, s, o);
        ss += __shfl_xor_sync(0xffffffffu, ss, o);
    }
    int warp = tid >> 5, lane = tid & 31;
    if (lane == 0) { sh[0][warp] = s; sh[1][warp] = ss; }
    __syncthreads();
    if (tid == 0) {
        float S = 0.f, SS = 0.f;
#pragma unroll
        for (int i = 0; i < 8; i++) { S += sh[0][i]; SS += sh[1][i]; }
        float mu  = S * (1.0f / D_MODEL);
        float var = SS * (1.0f / D_MODEL) - mu * mu;
        mu_s   = mu;
        rstd_s = rsqrtf(var + LN_EPS);
    }
    __syncthreads();
    float mu = mu_s, rstd = rstd_s;

    float4 g4 = *(const float4*)(gamma + tid * 4);
    float4 b4 = *(const float4*)(beta + tid * 4);
    float* yp = y + (size_t)tok * D_MODEL + tid * 4;
    float4 yo = *(float4*)yp;
    yo.x += w * ((v.x - mu) * rstd * g4.x + b4.x);
    yo.y += w * ((v.y - mu) * rstd * g4.y + b4.y);
    yo.z += w * ((v.z - mu) * rstd * g4.z + b4.z);
    yo.w += w * ((v.w - mu) * rstd * g4.w + b4.w);
    *(float4*)yp = yo;
}

// ---------------------------------------------------------------------------
extern "C" void kernel_launch(void* const* d_in, const int* in_sizes, int n_in,
                              void* d_out, int out_size) {
    const float* x     = (const float*)d_in[0];
    const float* gw    = (const float*)d_in[1];
    const float* w1    = (const float*)d_in[2];
    const float* b1    = (const float*)d_in[3];
    const float* w2    = (const float*)d_in[4];
    const float* b2    = (const float*)d_in[5];
    const float* gamma = (const float*)d_in[6];
    const float* beta  = (const float*)d_in[7];
    float* y = (float*)d_out;

    cudaFuncSetAttribute(gemm_mma<0>, cudaFuncAttributeMaxDynamicSharedMemorySize, 65536);
    cudaFuncSetAttribute(gemm_mma<1>, cudaFuncAttributeMaxDynamicSharedMemorySize, 65536);

    init_kernel<<<512, 256>>>(y);

    // split fp32 inputs into bf16 (hi, lo) pairs
    __nv_bfloat16 *xh, *xl, *w1h, *w1l, *w2h, *w2l;
    cudaGetSymbolAddress((void**)&xh,  g_xh);
    cudaGetSymbolAddress((void**)&xl,  g_xl);
    cudaGetSymbolAddress((void**)&w1h, g_w1h);
    cudaGetSymbolAddress((void**)&w1l, g_w1l);
    cudaGetSymbolAddress((void**)&w2h, g_w2h);
    cudaGetSymbolAddress((void**)&w2l, g_w2l);

    split_kernel<<<1024, 256>>>((const float4*)x,
                                (__nv_bfloat162*)xh, (__nv_bfloat162*)xl,
                                N_TOKENS * D_MODEL / 4);
    split_kernel<<<1024, 256>>>((const float4*)w1,
                                (__nv_bfloat162*)w1h, (__nv_bfloat162*)w1l,
                                N_EXPERTS * D_FF * D_MODEL / 4);
    split_kernel<<<1024, 256>>>((const float4*)w2,
                                (__nv_bfloat162*)w2h, (__nv_bfloat162*)w2l,
                                N_EXPERTS * D_MODEL * D_FF / 4);

    route_kernel<<<(N_TOKENS * 32) / 256, 256>>>(x, gw);

    for (int e = 0; e < N_EXPERTS; e++) {
        gemm_mma<0><<<dim3(D_FF / 128, N_TOKENS / 128), 256, 65536>>>(
            w1h + (size_t)e * D_FF * D_MODEL,
            w1l + (size_t)e * D_FF * D_MODEL,
            b1 + e * D_FF, x, e);
        gemm_mma<1><<<dim3(D_MODEL / 128, N_TOKENS / 128), 256, 65536>>>(
            w2h + (size_t)e * D_MODEL * D_FF,
            w2l + (size_t)e * D_MODEL * D_FF,
            b2 + e * D_MODEL, x, e);
        ln_accum_kernel<<<N_TOKENS, 256>>>(gamma + e * D_MODEL,
                                           beta + e * D_MODEL, y, e);
    }
}

// round 8
// speedup vs baseline: 4.2804x; 1.4447x over previous
#include <cuda_runtime.h>
#include <cuda_fp16.h>
#include <math.h>
#include <stdint.h>

#define N_TOKENS  16384
#define D_MODEL   1024
#define D_FF      2048
#define N_EXPERTS 4
#define LN_EPS    1e-6f

// ------------------------- static device scratch ---------------------------
__device__ __align__(16) __half g_xh[(size_t)N_TOKENS * D_MODEL];                 // x hi (fp16)
__device__ __align__(16) __half g_w1h[(size_t)N_EXPERTS * D_FF * D_MODEL];
__device__ __align__(16) __half g_w1l[(size_t)N_EXPERTS * D_FF * D_MODEL];
__device__ __align__(16) __half g_w2h[(size_t)N_EXPERTS * D_MODEL * D_FF];
__device__ __align__(16) __half g_w2l[(size_t)N_EXPERTS * D_MODEL * D_FF];
__device__ __align__(16) __half g_hh[(size_t)N_TOKENS * D_FF];                    // gelu out (fp16)
__device__ __align__(16) float  g_z[(size_t)N_TOKENS * D_MODEL];
__device__ float g_comb[N_TOKENS * N_EXPERTS];
__device__ int   g_idx[N_EXPERTS][N_TOKENS];
__device__ int   g_count[N_EXPERTS];

__device__ __forceinline__ float gelu_exact(float v) {
    return 0.5f * v * (1.0f + erff(v * 0.70710678118654752f));
}

// --------------------------- PTX helpers -----------------------------------
__device__ __forceinline__ void ldsm_x4(unsigned* r, unsigned addr) {
    asm volatile("ldmatrix.sync.aligned.m8n8.x4.shared.b16 {%0,%1,%2,%3}, [%4];"
                 : "=r"(r[0]), "=r"(r[1]), "=r"(r[2]), "=r"(r[3]) : "r"(addr));
}
__device__ __forceinline__ void mma16816(float* c, const unsigned* a, const unsigned* b) {
    asm volatile("mma.sync.aligned.m16n8k16.row.col.f32.f16.f16.f32 "
                 "{%0,%1,%2,%3}, {%4,%5,%6,%7}, {%8,%9}, {%0,%1,%2,%3};"
                 : "+f"(c[0]), "+f"(c[1]), "+f"(c[2]), "+f"(c[3])
                 : "r"(a[0]), "r"(a[1]), "r"(a[2]), "r"(a[3]), "r"(b[0]), "r"(b[1]));
}
#define CP_ASYNC16(s, g) \
    asm volatile("cp.async.cg.shared.global [%0], [%1], 16;" :: "r"(s), "l"(g) : "memory")
#define CP_COMMIT() asm volatile("cp.async.commit_group;" ::: "memory")
#define CP_WAIT2()  asm volatile("cp.async.wait_group 2;" ::: "memory")

// ---------------------------------------------------------------------------
__global__ void init_kernel(float* __restrict__ y) {
    int stride = gridDim.x * blockDim.x;
    for (int i = blockIdx.x * blockDim.x + threadIdx.x;
         i < N_TOKENS * D_MODEL; i += stride)
        y[i] = 0.0f;
    if (blockIdx.x == 0 && threadIdx.x < N_EXPERTS)
        g_count[threadIdx.x] = 0;
}

// fp32 -> fp16 hi only
__global__ void conv_hi_kernel(const float4* __restrict__ src,
                               __half2* __restrict__ hi, int n4) {
    int stride = gridDim.x * blockDim.x;
    for (int i = blockIdx.x * blockDim.x + threadIdx.x; i < n4; i += stride) {
        float4 v = src[i];
        hi[2 * i]     = __halves2half2(__float2half_rn(v.x), __float2half_rn(v.y));
        hi[2 * i + 1] = __halves2half2(__float2half_rn(v.z), __float2half_rn(v.w));
    }
}

// fp32 -> fp16 (hi, lo) pair
__global__ void split_kernel(const float4* __restrict__ src,
                             __half2* __restrict__ hi,
                             __half2* __restrict__ lo, int n4) {
    int stride = gridDim.x * blockDim.x;
    for (int i = blockIdx.x * blockDim.x + threadIdx.x; i < n4; i += stride) {
        float4 v = src[i];
        __half h0 = __float2half_rn(v.x), h1 = __float2half_rn(v.y);
        __half h2 = __float2half_rn(v.z), h3 = __float2half_rn(v.w);
        __half l0 = __float2half_rn(v.x - __half2float(h0));
        __half l1 = __float2half_rn(v.y - __half2float(h1));
        __half l2 = __float2half_rn(v.z - __half2float(h2));
        __half l3 = __float2half_rn(v.w - __half2float(h3));
        hi[2 * i]     = __halves2half2(h0, h1);
        hi[2 * i + 1] = __halves2half2(h2, h3);
        lo[2 * i]     = __halves2half2(l0, l1);
        lo[2 * i + 1] = __halves2half2(l2, l3);
    }
}

// ---------------------------------------------------------------------------
__global__ void route_kernel(const float* __restrict__ x,
                             const float* __restrict__ gw) {
    int warp = (blockIdx.x * blockDim.x + threadIdx.x) >> 5;
    int lane = threadIdx.x & 31;
    if (warp >= N_TOKENS) return;

    const float* xr = x + (size_t)warp * D_MODEL;
    float s0 = 0.f, s1 = 0.f, s2 = 0.f, s3 = 0.f;
    for (int i = lane; i < D_MODEL; i += 32) {
        float xv = xr[i];
        s0 += xv * gw[0 * D_MODEL + i];
        s1 += xv * gw[1 * D_MODEL + i];
        s2 += xv * gw[2 * D_MODEL + i];
        s3 += xv * gw[3 * D_MODEL + i];
    }
#pragma unroll
    for (int o = 16; o; o >>= 1) {
        s0 += __shfl_xor_sync(0xffffffffu, s0, o);
        s1 += __shfl_xor_sync(0xffffffffu, s1, o);
        s2 += __shfl_xor_sync(0xffffffffu, s2, o);
        s3 += __shfl_xor_sync(0xffffffffu, s3, o);
    }
    if (lane == 0) {
        float s[4] = {s0, s1, s2, s3};
        int i0 = 0;
#pragma unroll
        for (int e = 1; e < 4; e++) if (s[e] > s[i0]) i0 = e;
        int i1 = -1;
#pragma unroll
        for (int e = 0; e < 4; e++) {
            if (e == i0) continue;
            if (i1 < 0 || s[e] > s[i1]) i1 = e;
        }
        float m  = fmaxf(s[i0], s[i1]);
        float e0 = expf(s[i0] - m);
        float e1 = expf(s[i1] - m);
        float inv = 1.0f / (e0 + e1);
        float c[4] = {0.f, 0.f, 0.f, 0.f};
        c[i0] = e0 * inv;
        c[i1] = e1 * inv;
#pragma unroll
        for (int e = 0; e < 4; e++) g_comb[warp * N_EXPERTS + e] = c[e];
        int p0 = atomicAdd(&g_count[i0], 1);
        g_idx[i0][p0] = warp;
        int p1 = atomicAdd(&g_count[i1], 1);
        g_idx[i1][p1] = warp;
    }
}

// ---------------------------------------------------------------------------
// 2-pass fp16 split MMA GEMM: C = Ah @ (Bh + Bl)^T  (+epilogue)
// BM=128 BN=128 BK=32, 256 thr, 8 warps (2x4), warp tile 64x32,
// 4-stage cp.async ring, one __syncthreads per k-iter, XOR-swizzled smem.
// MODE 0: A = g_xh gathered rows, B = w1(hi/lo) -> g_hh = fp16(gelu(.+b1))
// MODE 1: A = g_hh compacted,     B = w2(hi/lo) -> g_z  = . + b2   (fp32)
// ---------------------------------------------------------------------------
#define NSTAGE   4
#define STAGE_SZ 24576
#define OFF_A    0
#define OFF_BH   8192
#define OFF_BL   16384
#define GEMM_SMEM (NSTAGE * STAGE_SZ)

template <int MODE>
__global__ __launch_bounds__(256, 2)
void gemm_mma(const __half* __restrict__ Bh,
              const __half* __restrict__ Bl,
              const float* __restrict__ bias, int e) {
    constexpr int K  = (MODE == 0) ? D_MODEL : D_FF;
    constexpr int NO = (MODE == 0) ? D_FF    : D_MODEL;
    constexpr int KT = K / 32;

    const int count = g_count[e];
    const int m0 = blockIdx.y * 128;
    if (m0 >= count) return;
    const int n0 = blockIdx.x * 128;

    extern __shared__ __align__(16) char dyn[];
    const unsigned sbase = (unsigned)__cvta_generic_to_shared(dyn);

    const int tid  = threadIdx.x;
    const int lane = tid & 31;
    const int wid  = tid >> 5;
    const int m_warp = (wid >> 2) * 64;   // 0 or 64
    const int n_warp = (wid & 3) * 32;    // 0..96

    // ---- cp.async assignment: thread -> rows rA0, rA0+64; 16B chunk ck
    const int rA0 = tid >> 2;          // 0..63
    const int rA1 = rA0 + 64;
    const int ck  = tid & 3;           // 16B chunk within 64B row

    const __half* Ag = (MODE == 0) ? g_xh : g_hh;
    int gr0 = m0 + rA0, gr1 = m0 + rA1;
    int s0, s1;
    if (MODE == 0) {
        s0 = g_idx[e][(gr0 < count) ? gr0 : 0];
        s1 = g_idx[e][(gr1 < count) ? gr1 : 0];
    } else {
        s0 = (gr0 < count) ? gr0 : 0;
        s1 = (gr1 < count) ? gr1 : 0;
    }
    const __half* pA0  = Ag + (size_t)s0 * K + ck * 8;
    const __half* pA1  = Ag + (size_t)s1 * K + ck * 8;
    const __half* pBh0 = Bh + (size_t)(n0 + rA0) * K + ck * 8;
    const __half* pBh1 = Bh + (size_t)(n0 + rA1) * K + ck * 8;
    const __half* pBl0 = Bl + (size_t)(n0 + rA0) * K + ck * 8;
    const __half* pBl1 = Bl + (size_t)(n0 + rA1) * K + ck * 8;

    const unsigned sOf0 = rA0 * 64 + ((ck ^ ((rA0 >> 1) & 3)) << 4);
    const unsigned sOf1 = rA1 * 64 + ((ck ^ ((rA1 >> 1) & 3)) << 4);

    // ---- ldmatrix offsets
    unsigned rowtermA[4], swzA[4];
#pragma unroll
    for (int mt = 0; mt < 4; mt++) {
        int r = m_warp + mt * 16 + (lane & 7) + ((lane >> 3) & 1) * 8;
        rowtermA[mt] = r * 64;
        swzA[mt]     = (r >> 1) & 3;
    }
    const unsigned g2A = lane >> 4;  // 0/1 within 16-lane halves
    unsigned offB[4];
#pragma unroll
    for (int nt = 0; nt < 4; nt++) {
        int r = n_warp + nt * 8 + (lane & 7);
        unsigned g = lane >> 3;      // 0..3 -> k-chunks
        offB[nt] = r * 64 + ((g ^ ((r >> 1) & 3)) << 4);
    }

    float acc[4][4][4];
#pragma unroll
    for (int mt = 0; mt < 4; mt++)
#pragma unroll
        for (int nt = 0; nt < 4; nt++)
#pragma unroll
            for (int i = 0; i < 4; i++) acc[mt][nt][i] = 0.f;

#define ISSUE(slot, kt)                                            \
    do {                                                           \
        unsigned sb = sbase + (slot) * STAGE_SZ;                   \
        int kb = (kt) * 32;                                        \
        CP_ASYNC16(sb + OFF_A  + sOf0, pA0  + kb);                 \
        CP_ASYNC16(sb + OFF_A  + sOf1, pA1  + kb);                 \
        CP_ASYNC16(sb + OFF_BH + sOf0, pBh0 + kb);                 \
        CP_ASYNC16(sb + OFF_BH + sOf1, pBh1 + kb);                 \
        CP_ASYNC16(sb + OFF_BL + sOf0, pBl0 + kb);                 \
        CP_ASYNC16(sb + OFF_BL + sOf1, pBl1 + kb);                 \
    } while (0)

    ISSUE(0, 0); CP_COMMIT();
    ISSUE(1, 1); CP_COMMIT();
    ISSUE(2, 2); CP_COMMIT();

    int slot = 0;
    for (int kt = 0; kt < KT; kt++) {
        CP_WAIT2();
        __syncthreads();

        const unsigned sb = sbase + slot * STAGE_SZ;
        unsigned bh[4][4], bl[4][4];
#pragma unroll
        for (int nt = 0; nt < 4; nt++) {
            ldsm_x4(bh[nt], sb + OFF_BH + offB[nt]);
            ldsm_x4(bl[nt], sb + OFF_BL + offB[nt]);
        }
#pragma unroll
        for (int k16 = 0; k16 < 2; k16++) {
#pragma unroll
            for (int mt = 0; mt < 4; mt++) {
                unsigned offA = rowtermA[mt] + (((k16 * 2 + g2A) ^ swzA[mt]) << 4);
                unsigned ah[4];
                ldsm_x4(ah, sb + OFF_A + offA);
#pragma unroll
                for (int nt = 0; nt < 4; nt++) {
                    mma16816(acc[mt][nt], ah, &bh[nt][k16 * 2]);
                    mma16816(acc[mt][nt], ah, &bl[nt][k16 * 2]);
                }
            }
        }
        if (kt + 3 < KT) {
            int ws = slot - 1; if (ws < 0) ws = NSTAGE - 1;
            ISSUE(ws, kt + 3);
        }
        CP_COMMIT();
        slot++; if (slot == NSTAGE) slot = 0;
    }

    // ---- epilogue
#pragma unroll
    for (int nt = 0; nt < 4; nt++) {
        const int col = n0 + n_warp + nt * 8 + (lane & 3) * 2;
        const float bz0 = __ldg(&bias[col]), bz1 = __ldg(&bias[col + 1]);
#pragma unroll
        for (int mt = 0; mt < 4; mt++) {
#pragma unroll
            for (int half_i = 0; half_i < 2; half_i++) {
                int gr = m0 + m_warp + mt * 16 + (lane >> 2) + half_i * 8;
                if (gr >= count) continue;
                float v0 = acc[mt][nt][half_i * 2 + 0] + bz0;
                float v1 = acc[mt][nt][half_i * 2 + 1] + bz1;
                if (MODE == 0) {
                    v0 = gelu_exact(v0);
                    v1 = gelu_exact(v1);
                    *(__half2*)&g_hh[(size_t)gr * NO + col] =
                        __halves2half2(__float2half_rn(v0), __float2half_rn(v1));
                } else {
                    float2 o; o.x = v0; o.y = v1;
                    *(float2*)&g_z[(size_t)gr * NO + col] = o;
                }
            }
        }
    }
#undef ISSUE
}

// ---------------------------------------------------------------------------
// LN of (x[tok] + z) + weighted accumulate into y.
// ---------------------------------------------------------------------------
__global__ void ln_accum_kernel(const float* __restrict__ x,
                                const float* __restrict__ gamma,
                                const float* __restrict__ beta,
                                float* __restrict__ y, int e) {
    int r = blockIdx.x;
    if (r >= g_count[e]) return;
    int tok = g_idx[e][r];
    float w = g_comb[tok * N_EXPERTS + e];

    int tid = threadIdx.x;
    float4 z4 = *(const float4*)(g_z + (size_t)r * D_MODEL + tid * 4);
    float4 x4 = *(const float4*)(x + (size_t)tok * D_MODEL + tid * 4);
    float4 v;
    v.x = z4.x + x4.x; v.y = z4.y + x4.y; v.z = z4.z + x4.z; v.w = z4.w + x4.w;
    float s  = v.x + v.y + v.z + v.w;
    float ss = v.x * v.x + v.y * v.y + v.z * v.z + v.w * v.w;

    __shared__ float sh[2][8];
    __shared__ float mu_s, rstd_s;
#pragma unroll
    for (int o = 16; o; o >>= 1) {
        s  += __shfl_xor_sync(0xffffffffu, s, o);
        ss += __shfl_xor_sync(0xffffffffu, ss, o);
    }
    int warp = tid >> 5, lane = tid & 31;
    if (lane == 0) { sh[0][warp] = s; sh[1][warp] = ss; }
    __syncthreads();
    if (tid == 0) {
        float S = 0.f, SS = 0.f;
#pragma unroll
        for (int i = 0; i < 8; i++) { S += sh[0][i]; SS += sh[1][i]; }
        float mu  = S * (1.0f / D_MODEL);
        float var = SS * (1.0f / D_MODEL) - mu * mu;
        mu_s   = mu;
        rstd_s = rsqrtf(var + LN_EPS);
    }
    __syncthreads();
    float mu = mu_s, rstd = rstd_s;

    float4 g4 = *(const float4*)(gamma + tid * 4);
    float4 b4 = *(const float4*)(beta + tid * 4);
    float* yp = y + (size_t)tok * D_MODEL + tid * 4;
    float4 yo = *(float4*)yp;
    yo.x += w * ((v.x - mu) * rstd * g4.x + b4.x);
    yo.y += w * ((v.y - mu) * rstd * g4.y + b4.y);
    yo.z += w * ((v.z - mu) * rstd * g4.z + b4.z);
    yo.w += w * ((v.w - mu) * rstd * g4.w + b4.w);
    *(float4*)yp = yo;
}

// ---------------------------------------------------------------------------
extern "C" void kernel_launch(void* const* d_in, const int* in_sizes, int n_in,
                              void* d_out, int out_size) {
    const float* x     = (const float*)d_in[0];
    const float* gw    = (const float*)d_in[1];
    const float* w1    = (const float*)d_in[2];
    const float* b1    = (const float*)d_in[3];
    const float* w2    = (const float*)d_in[4];
    const float* b2    = (const float*)d_in[5];
    const float* gamma = (const float*)d_in[6];
    const float* beta  = (const float*)d_in[7];
    float* y = (float*)d_out;

    cudaFuncSetAttribute(gemm_mma<0>, cudaFuncAttributeMaxDynamicSharedMemorySize, GEMM_SMEM);
    cudaFuncSetAttribute(gemm_mma<1>, cudaFuncAttributeMaxDynamicSharedMemorySize, GEMM_SMEM);

    __half *xh, *w1h, *w1l, *w2h, *w2l;
    cudaGetSymbolAddress((void**)&xh,  g_xh);
    cudaGetSymbolAddress((void**)&w1h, g_w1h);
    cudaGetSymbolAddress((void**)&w1l, g_w1l);
    cudaGetSymbolAddress((void**)&w2h, g_w2h);
    cudaGetSymbolAddress((void**)&w2l, g_w2l);

    init_kernel<<<512, 256>>>(y);
    conv_hi_kernel<<<1024, 256>>>((const float4*)x, (__half2*)xh,
                                  N_TOKENS * D_MODEL / 4);
    split_kernel<<<1024, 256>>>((const float4*)w1, (__half2*)w1h, (__half2*)w1l,
                                N_EXPERTS * D_FF * D_MODEL / 4);
    split_kernel<<<1024, 256>>>((const float4*)w2, (__half2*)w2h, (__half2*)w2l,
                                N_EXPERTS * D_MODEL * D_FF / 4);
    route_kernel<<<(N_TOKENS * 32) / 256, 256>>>(x, gw);

    for (int e = 0; e < N_EXPERTS; e++) {
        gemm_mma<0><<<dim3(D_FF / 128, N_TOKENS / 128), 256, GEMM_SMEM>>>(
            w1h + (size_t)e * D_FF * D_MODEL,
            w1l + (size_t)e * D_FF * D_MODEL,
            b1 + e * D_FF, e);
        gemm_mma<1><<<dim3(D_MODEL / 128, N_TOKENS / 128), 256, GEMM_SMEM>>>(
            w2h + (size_t)e * D_MODEL * D_FF,
            w2l + (size_t)e * D_MODEL * D_FF,
            b2 + e * D_MODEL, e);
        ln_accum_kernel<<<N_TOKENS, 256>>>(x, gamma + e * D_MODEL,
                                           beta + e * D_MODEL, y, e);
    }
}

// round 11
// speedup vs baseline: 7.0906x; 1.6565x over previous
#include <cuda_runtime.h>
#include <cuda_fp16.h>
#include <math.h>
#include <stdint.h>

#define N_TOKENS  16384
#define D_MODEL   1024
#define D_FF      2048
#define N_EXPERTS 4
#define LN_EPS    1e-6f

// ------------------------- static device scratch ---------------------------
__device__ __align__(16) __half g_xh[(size_t)N_TOKENS * D_MODEL];            // x (fp16)
__device__ __align__(16) __half g_w1h[(size_t)N_EXPERTS * D_FF * D_MODEL];   // w1 (fp16)
__device__ __align__(16) __half g_w2h[(size_t)N_EXPERTS * D_MODEL * D_FF];   // w2 (fp16)
__device__ __align__(16) __half g_hh[(size_t)N_TOKENS * D_FF];               // gelu out (fp16)
__device__ __align__(16) float  g_z[(size_t)N_TOKENS * D_MODEL];
__device__ float g_comb[N_TOKENS * N_EXPERTS];
__device__ int   g_idx[N_EXPERTS][N_TOKENS];
__device__ int   g_count[N_EXPERTS];

__device__ __forceinline__ float gelu_exact(float v) {
    return 0.5f * v * (1.0f + erff(v * 0.70710678118654752f));
}

// --------------------------- PTX helpers -----------------------------------
__device__ __forceinline__ void ldsm_x4(unsigned* r, unsigned addr) {
    asm volatile("ldmatrix.sync.aligned.m8n8.x4.shared.b16 {%0,%1,%2,%3}, [%4];"
                 : "=r"(r[0]), "=r"(r[1]), "=r"(r[2]), "=r"(r[3]) : "r"(addr));
}
__device__ __forceinline__ void mma16816(float* c, const unsigned* a, const unsigned* b) {
    asm volatile("mma.sync.aligned.m16n8k16.row.col.f32.f16.f16.f32 "
                 "{%0,%1,%2,%3}, {%4,%5,%6,%7}, {%8,%9}, {%0,%1,%2,%3};"
                 : "+f"(c[0]), "+f"(c[1]), "+f"(c[2]), "+f"(c[3])
                 : "r"(a[0]), "r"(a[1]), "r"(a[2]), "r"(a[3]), "r"(b[0]), "r"(b[1]));
}
#define CP_ASYNC16(s, g) \
    asm volatile("cp.async.cg.shared.global [%0], [%1], 16;" :: "r"(s), "l"(g) : "memory")
#define CP_COMMIT() asm volatile("cp.async.commit_group;" ::: "memory")
#define CP_WAIT3()  asm volatile("cp.async.wait_group 3;" ::: "memory")

// ---------------------------------------------------------------------------
__global__ void init_kernel(float* __restrict__ y) {
    int stride = gridDim.x * blockDim.x;
    for (int i = blockIdx.x * blockDim.x + threadIdx.x;
         i < N_TOKENS * D_MODEL; i += stride)
        y[i] = 0.0f;
    if (blockIdx.x == 0 && threadIdx.x < N_EXPERTS)
        g_count[threadIdx.x] = 0;
}

// fp32 -> fp16 (round-to-nearest)
__global__ void conv_hi_kernel(const float4* __restrict__ src,
                               __half2* __restrict__ hi, int n4) {
    int stride = gridDim.x * blockDim.x;
    for (int i = blockIdx.x * blockDim.x + threadIdx.x; i < n4; i += stride) {
        float4 v = src[i];
        hi[2 * i]     = __halves2half2(__float2half_rn(v.x), __float2half_rn(v.y));
        hi[2 * i + 1] = __halves2half2(__float2half_rn(v.z), __float2half_rn(v.w));
    }
}

// ---------------------------------------------------------------------------
__global__ void route_kernel(const float* __restrict__ x,
                             const float* __restrict__ gw) {
    int warp = (blockIdx.x * blockDim.x + threadIdx.x) >> 5;
    int lane = threadIdx.x & 31;
    if (warp >= N_TOKENS) return;

    const float* xr = x + (size_t)warp * D_MODEL;
    float s0 = 0.f, s1 = 0.f, s2 = 0.f, s3 = 0.f;
    for (int i = lane; i < D_MODEL; i += 32) {
        float xv = xr[i];
        s0 += xv * gw[0 * D_MODEL + i];
        s1 += xv * gw[1 * D_MODEL + i];
        s2 += xv * gw[2 * D_MODEL + i];
        s3 += xv * gw[3 * D_MODEL + i];
    }
#pragma unroll
    for (int o = 16; o; o >>= 1) {
        s0 += __shfl_xor_sync(0xffffffffu, s0, o);
        s1 += __shfl_xor_sync(0xffffffffu, s1, o);
        s2 += __shfl_xor_sync(0xffffffffu, s2, o);
        s3 += __shfl_xor_sync(0xffffffffu, s3, o);
    }
    if (lane == 0) {
        float s[4] = {s0, s1, s2, s3};
        int i0 = 0;
#pragma unroll
        for (int e = 1; e < 4; e++) if (s[e] > s[i0]) i0 = e;
        int i1 = -1;
#pragma unroll
        for (int e = 0; e < 4; e++) {
            if (e == i0) continue;
            if (i1 < 0 || s[e] > s[i1]) i1 = e;
        }
        float m  = fmaxf(s[i0], s[i1]);
        float e0 = expf(s[i0] - m);
        float e1 = expf(s[i1] - m);
        float inv = 1.0f / (e0 + e1);
        float c[4] = {0.f, 0.f, 0.f, 0.f};
        c[i0] = e0 * inv;
        c[i1] = e1 * inv;
#pragma unroll
        for (int e = 0; e < 4; e++) g_comb[warp * N_EXPERTS + e] = c[e];
        int p0 = atomicAdd(&g_count[i0], 1);
        g_idx[i0][p0] = warp;
        int p1 = atomicAdd(&g_count[i1], 1);
        g_idx[i1][p1] = warp;
    }
}

// ---------------------------------------------------------------------------
// Single-pass fp16 MMA GEMM: C = Ah @ Bh^T (+epilogue)
// BM=128 BN=128 BK=32, 256 thr, 8 warps (2x4), warp tile 64x32,
// 5-stage cp.async ring (4 prefetched), one __syncthreads per k-iter,
// XOR-swizzled smem for conflict-free ldmatrix.
// MODE 0: A = g_xh gathered rows, B = w1 -> g_hh = fp16(gelu(.+b1))
// MODE 1: A = g_hh compacted,     B = w2 -> g_z  = . + b2   (fp32)
// ---------------------------------------------------------------------------
#define NSTAGE   5
#define STAGE_SZ 16384
#define OFF_A    0
#define OFF_B    8192
#define GEMM_SMEM (NSTAGE * STAGE_SZ)

template <int MODE>
__global__ __launch_bounds__(256, 2)
void gemm_mma(const __half* __restrict__ Bg,
              const float* __restrict__ bias, int e) {
    constexpr int K  = (MODE == 0) ? D_MODEL : D_FF;
    constexpr int NO = (MODE == 0) ? D_FF    : D_MODEL;
    constexpr int KT = K / 32;

    const int count = g_count[e];
    const int m0 = blockIdx.y * 128;
    if (m0 >= count) return;
    const int n0 = blockIdx.x * 128;

    extern __shared__ __align__(16) char dyn[];
    const unsigned sbase = (unsigned)__cvta_generic_to_shared(dyn);

    const int tid  = threadIdx.x;
    const int lane = tid & 31;
    const int wid  = tid >> 5;
    const int m_warp = (wid >> 2) * 64;   // 0 or 64
    const int n_warp = (wid & 3) * 32;    // 0..96

    // ---- cp.async assignment: thread -> rows rA0, rA0+64; 16B chunk ck
    const int rA0 = tid >> 2;          // 0..63
    const int rA1 = rA0 + 64;
    const int ck  = tid & 3;           // 16B chunk within 64B row

    const __half* Ag = (MODE == 0) ? g_xh : g_hh;
    int gr0 = m0 + rA0, gr1 = m0 + rA1;
    int s0, s1;
    if (MODE == 0) {
        s0 = g_idx[e][(gr0 < count) ? gr0 : 0];
        s1 = g_idx[e][(gr1 < count) ? gr1 : 0];
    } else {
        s0 = (gr0 < count) ? gr0 : 0;
        s1 = (gr1 < count) ? gr1 : 0;
    }
    const __half* pA0 = Ag + (size_t)s0 * K + ck * 8;
    const __half* pA1 = Ag + (size_t)s1 * K + ck * 8;
    const __half* pB0 = Bg + (size_t)(n0 + rA0) * K + ck * 8;
    const __half* pB1 = Bg + (size_t)(n0 + rA1) * K + ck * 8;

    const unsigned sOf0 = rA0 * 64 + ((ck ^ ((rA0 >> 1) & 3)) << 4);
    const unsigned sOf1 = rA1 * 64 + ((ck ^ ((rA1 >> 1) & 3)) << 4);

    // ---- ldmatrix offsets
    unsigned rowtermA[4], swzA[4];
#pragma unroll
    for (int mt = 0; mt < 4; mt++) {
        int r = m_warp + mt * 16 + (lane & 7) + ((lane >> 3) & 1) * 8;
        rowtermA[mt] = r * 64;
        swzA[mt]     = (r >> 1) & 3;
    }
    const unsigned g2A = lane >> 4;  // 0/1 within 16-lane halves
    unsigned offB[4];
#pragma unroll
    for (int nt = 0; nt < 4; nt++) {
        int r = n_warp + nt * 8 + (lane & 7);
        unsigned g = lane >> 3;      // 0..3 -> k-chunks
        offB[nt] = r * 64 + ((g ^ ((r >> 1) & 3)) << 4);
    }

    float acc[4][4][4];
#pragma unroll
    for (int mt = 0; mt < 4; mt++)
#pragma unroll
        for (int nt = 0; nt < 4; nt++)
#pragma unroll
            for (int i = 0; i < 4; i++) acc[mt][nt][i] = 0.f;

#define ISSUE(slot, kt)                                            \
    do {                                                           \
        unsigned sb = sbase + (slot) * STAGE_SZ;                   \
        int kb = (kt) * 32;                                        \
        CP_ASYNC16(sb + OFF_A + sOf0, pA0 + kb);                   \
        CP_ASYNC16(sb + OFF_A + sOf1, pA1 + kb);                   \
        CP_ASYNC16(sb + OFF_B + sOf0, pB0 + kb);                   \
        CP_ASYNC16(sb + OFF_B + sOf1, pB1 + kb);                   \
    } while (0)

    ISSUE(0, 0); CP_COMMIT();
    ISSUE(1, 1); CP_COMMIT();
    ISSUE(2, 2); CP_COMMIT();
    ISSUE(3, 3); CP_COMMIT();

    int slot = 0;
    for (int kt = 0; kt < KT; kt++) {
        CP_WAIT3();
        __syncthreads();

        const unsigned sb = sbase + slot * STAGE_SZ;
        unsigned bfr[4][4];
#pragma unroll
        for (int nt = 0; nt < 4; nt++)
            ldsm_x4(bfr[nt], sb + OFF_B + offB[nt]);
#pragma unroll
        for (int k16 = 0; k16 < 2; k16++) {
#pragma unroll
            for (int mt = 0; mt < 4; mt++) {
                unsigned offA = rowtermA[mt] + (((k16 * 2 + g2A) ^ swzA[mt]) << 4);
                unsigned ah[4];
                ldsm_x4(ah, sb + OFF_A + offA);
#pragma unroll
                for (int nt = 0; nt < 4; nt++)
                    mma16816(acc[mt][nt], ah, &bfr[nt][k16 * 2]);
            }
        }
        if (kt + 4 < KT) {
            int ws = slot - 1; if (ws < 0) ws = NSTAGE - 1;
            ISSUE(ws, kt + 4);
        }
        CP_COMMIT();
        slot++; if (slot == NSTAGE) slot = 0;
    }

    // ---- epilogue
#pragma unroll
    for (int nt = 0; nt < 4; nt++) {
        const int col = n0 + n_warp + nt * 8 + (lane & 3) * 2;
        const float bz0 = __ldg(&bias[col]), bz1 = __ldg(&bias[col + 1]);
#pragma unroll
        for (int mt = 0; mt < 4; mt++) {
#pragma unroll
            for (int half_i = 0; half_i < 2; half_i++) {
                int gr = m0 + m_warp + mt * 16 + (lane >> 2) + half_i * 8;
                if (gr >= count) continue;
                float v0 = acc[mt][nt][half_i * 2 + 0] + bz0;
                float v1 = acc[mt][nt][half_i * 2 + 1] + bz1;
                if (MODE == 0) {
                    v0 = gelu_exact(v0);
                    v1 = gelu_exact(v1);
                    *(__half2*)&g_hh[(size_t)gr * NO + col] =
                        __halves2half2(__float2half_rn(v0), __float2half_rn(v1));
                } else {
                    float2 o; o.x = v0; o.y = v1;
                    *(float2*)&g_z[(size_t)gr * NO + col] = o;
                }
            }
        }
    }
#undef ISSUE
}

// ---------------------------------------------------------------------------
// LN of (x[tok] + z) + weighted accumulate into y.
// ---------------------------------------------------------------------------
__global__ void ln_accum_kernel(const float* __restrict__ x,
                                const float* __restrict__ gamma,
                                const float* __restrict__ beta,
                                float* __restrict__ y, int e) {
    int r = blockIdx.x;
    if (r >= g_count[e]) return;
    int tok = g_idx[e][r];
    float w = g_comb[tok * N_EXPERTS + e];

    int tid = threadIdx.x;
    float4 z4 = *(const float4*)(g_z + (size_t)r * D_MODEL + tid * 4);
    float4 x4 = *(const float4*)(x + (size_t)tok * D_MODEL + tid * 4);
    float4 v;
    v.x = z4.x + x4.x; v.y = z4.y + x4.y; v.z = z4.z + x4.z; v.w = z4.w + x4.w;
    float s  = v.x + v.y + v.z + v.w;
    float ss = v.x * v.x + v.y * v.y + v.z * v.z + v.w * v.w;

    __shared__ float sh[2][8];
    __shared__ float mu_s, rstd_s;
#pragma unroll
    for (int o = 16; o; o >>= 1) {
        s  += __shfl_xor_sync(0xffffffffu, s, o);
        ss += __shfl_xor_sync(0xffffffffu, ss, o);
    }
    int warp = tid >> 5, lane = tid & 31;
    if (lane == 0) { sh[0][warp] = s; sh[1][warp] = ss; }
    __syncthreads();
    if (tid == 0) {
        float S = 0.f, SS = 0.f;
#pragma unroll
        for (int i = 0; i < 8; i++) { S += sh[0][i]; SS += sh[1][i]; }
        float mu  = S * (1.0f / D_MODEL);
        float var = SS * (1.0f / D_MODEL) - mu * mu;
        mu_s   = mu;
        rstd_s = rsqrtf(var + LN_EPS);
    }
    __syncthreads();
    float mu = mu_s, rstd = rstd_s;

    float4 g4 = *(const float4*)(gamma + tid * 4);
    float4 b4 = *(const float4*)(beta + tid * 4);
    float* yp = y + (size_t)tok * D_MODEL + tid * 4;
    float4 yo = *(float4*)yp;
    yo.x += w * ((v.x - mu) * rstd * g4.x + b4.x);
    yo.y += w * ((v.y - mu) * rstd * g4.y + b4.y);
    yo.z += w * ((v.z - mu) * rstd * g4.z + b4.z);
    yo.w += w * ((v.w - mu) * rstd * g4.w + b4.w);
    *(float4*)yp = yo;
}

// ---------------------------------------------------------------------------
extern "C" void kernel_launch(void* const* d_in, const int* in_sizes, int n_in,
                              void* d_out, int out_size) {
    const float* x     = (const float*)d_in[0];
    const float* gw    = (const float*)d_in[1];
    const float* w1    = (const float*)d_in[2];
    const float* b1    = (const float*)d_in[3];
    const float* w2    = (const float*)d_in[4];
    const float* b2    = (const float*)d_in[5];
    const float* gamma = (const float*)d_in[6];
    const float* beta  = (const float*)d_in[7];
    float* y = (float*)d_out;

    cudaFuncSetAttribute(gemm_mma<0>, cudaFuncAttributeMaxDynamicSharedMemorySize, GEMM_SMEM);
    cudaFuncSetAttribute(gemm_mma<1>, cudaFuncAttributeMaxDynamicSharedMemorySize, GEMM_SMEM);

    __half *xh, *w1h, *w2h;
    cudaGetSymbolAddress((void**)&xh,  g_xh);
    cudaGetSymbolAddress((void**)&w1h, g_w1h);
    cudaGetSymbolAddress((void**)&w2h, g_w2h);

    init_kernel<<<512, 256>>>(y);
    conv_hi_kernel<<<1024, 256>>>((const float4*)x, (__half2*)xh,
                                  N_TOKENS * D_MODEL / 4);
    conv_hi_kernel<<<1024, 256>>>((const float4*)w1, (__half2*)w1h,
                                  N_EXPERTS * D_FF * D_MODEL / 4);
    conv_hi_kernel<<<1024, 256>>>((const float4*)w2, (__half2*)w2h,
                                  N_EXPERTS * D_MODEL * D_FF / 4);
    route_kernel<<<(N_TOKENS * 32) / 256, 256>>>(x, gw);

    for (int e = 0; e < N_EXPERTS; e++) {
        gemm_mma<0><<<dim3(D_FF / 128, N_TOKENS / 128), 256, GEMM_SMEM>>>(
            w1h + (size_t)e * D_FF * D_MODEL, b1 + e * D_FF, e);
        gemm_mma<1><<<dim3(D_MODEL / 128, N_TOKENS / 128), 256, GEMM_SMEM>>>(
            w2h + (size_t)e * D_MODEL * D_FF, b2 + e * D_MODEL, e);
        ln_accum_kernel<<<N_TOKENS, 256>>>(x, gamma + e * D_MODEL,
                                           beta + e * D_MODEL, y, e);
    }
}